// round 1
// baseline (speedup 1.0000x reference)
#include <cuda_runtime.h>
#include <math.h>

// Problem constants
#define BB   2
#define N0c  1536
#define N1c  512
#define NTc  2048          // N0 + N1
#define Hc   16
#define Dc   64            // head dim
#define DIc  1024          // H * D
#define D0c  1024
#define D1c  512

// Scratch (device globals: allocation-free)
__device__ float g_q[BB * Hc * NTc * Dc];   // [b,h,N,D]
__device__ float g_k[BB * Hc * NTc * Dc];
__device__ float g_v[BB * Hc * NTc * Dc];
__device__ float g_o[BB * NTc * DIc];       // [b,N,H*D] merged heads

// ---------------------------------------------------------------------------
// QKV GEMM: QKV[M,3072] = X[M,K] @ W[K,3072], epilogue scatters into g_q/g_k/g_v
// M = B*n_m (divisible by 128), K = d_in (divisible by 8)
// column c: qkv=c>>10, h=(c>>6)&15, d=c&63
// row r: bi = r>=n_m, t = r - bi*n_m, tok = t (+N0 for mod1)
// ---------------------------------------------------------------------------
__global__ __launch_bounds__(256) void qkv_gemm(
    const float* __restrict__ X, const float* __restrict__ W,
    int K, int n_m, int mod)
{
    __shared__ __align__(16) float As[8][132];
    __shared__ __align__(16) float Bs[8][128];

    const int tid = threadIdx.x;
    const int bx = blockIdx.x, by = blockIdx.y;
    const int tx = tid & 15, ty = tid >> 4;

    float acc[8][8];
#pragma unroll
    for (int i = 0; i < 8; i++)
#pragma unroll
        for (int j = 0; j < 8; j++) acc[i][j] = 0.f;

    const int aRow = tid >> 1, aCol = (tid & 1) * 4;
    const int bRow = tid >> 5, bCol = (tid & 31) * 4;
    const float* Aptr = X + (size_t)(by * 128 + aRow) * K + aCol;
    const float* Bptr = W + (size_t)bRow * 3072 + bx * 128 + bCol;

    for (int kk = 0; kk < K; kk += 8) {
        float4 av = *(const float4*)(Aptr + kk);
        float4 bv = *(const float4*)(Bptr + (size_t)kk * 3072);
        As[aCol + 0][aRow] = av.x;
        As[aCol + 1][aRow] = av.y;
        As[aCol + 2][aRow] = av.z;
        As[aCol + 3][aRow] = av.w;
        *(float4*)&Bs[bRow][bCol] = bv;
        __syncthreads();
#pragma unroll
        for (int k = 0; k < 8; k++) {
            float a[8], b[8];
            *(float4*)&a[0] = *(const float4*)&As[k][ty * 8];
            *(float4*)&a[4] = *(const float4*)&As[k][ty * 8 + 4];
            *(float4*)&b[0] = *(const float4*)&Bs[k][tx * 8];
            *(float4*)&b[4] = *(const float4*)&Bs[k][tx * 8 + 4];
#pragma unroll
            for (int i = 0; i < 8; i++)
#pragma unroll
                for (int j = 0; j < 8; j++) acc[i][j] += a[i] * b[j];
        }
        __syncthreads();
    }

    // Epilogue: scatter into q/k/v [b,h,NT,D]; 8 cols stay inside one (qkv,h)
    const int c0  = bx * 128 + tx * 8;
    const int qkv = c0 >> 10;
    const int h   = (c0 >> 6) & (Hc - 1);
    const int d   = c0 & (Dc - 1);
    float* dst = (qkv == 0) ? g_q : ((qkv == 1) ? g_k : g_v);

#pragma unroll
    for (int i = 0; i < 8; i++) {
        const int r   = by * 128 + ty * 8 + i;
        const int bi  = (r >= n_m) ? 1 : 0;
        const int tok = r - bi * n_m + (mod ? N0c : 0);
        float* p = dst + ((size_t)((bi * Hc + h) * NTc + tok)) * Dc + d;
        float4 w0 = make_float4(acc[i][0], acc[i][1], acc[i][2], acc[i][3]);
        float4 w1 = make_float4(acc[i][4], acc[i][5], acc[i][6], acc[i][7]);
        *(float4*)p       = w0;
        *(float4*)(p + 4) = w1;
    }
}

// ---------------------------------------------------------------------------
// QK RMSNorm: per row of 64: x / max(||x||,eps) * gamma * 8
// one warp per row; handles both q and k
// ---------------------------------------------------------------------------
__global__ __launch_bounds__(256) void qk_rmsnorm(
    const float* __restrict__ qg0, const float* __restrict__ kg0,
    const float* __restrict__ qg1, const float* __restrict__ kg1)
{
    const int warp = (blockIdx.x * blockDim.x + threadIdx.x) >> 5;
    const int lane = threadIdx.x & 31;
    if (warp >= BB * Hc * NTc) return;

    const int h   = (warp >> 11) & (Hc - 1);   // NT = 2048 = 2^11
    const int tok = warp & (NTc - 1);
    const int mod = (tok >= N0c) ? 1 : 0;
    const float* qg = mod ? qg1 : qg0;
    const float* kg = mod ? kg1 : kg0;
    const float gq0 = qg[h * 64 + lane], gq1 = qg[h * 64 + lane + 32];
    const float gk0 = kg[h * 64 + lane], gk1 = kg[h * 64 + lane + 32];

    // q row
    {
        float* p = g_q + (size_t)warp * 64;
        float a = p[lane], b = p[lane + 32];
        float ss = a * a + b * b;
#pragma unroll
        for (int off = 16; off > 0; off >>= 1)
            ss += __shfl_xor_sync(0xFFFFFFFFu, ss, off);
        float s = 8.0f / fmaxf(sqrtf(ss), 1e-12f);
        p[lane]      = a * s * gq0;
        p[lane + 32] = b * s * gq1;
    }
    // k row
    {
        float* p = g_k + (size_t)warp * 64;
        float a = p[lane], b = p[lane + 32];
        float ss = a * a + b * b;
#pragma unroll
        for (int off = 16; off > 0; off >>= 1)
            ss += __shfl_xor_sync(0xFFFFFFFFu, ss, off);
        float s = 8.0f / fmaxf(sqrtf(ss), 1e-12f);
        p[lane]      = a * s * gk0;
        p[lane + 32] = b * s * gk1;
    }
}

// ---------------------------------------------------------------------------
// Attention: grid (NT/128, H, B), 128 threads, 1 query per thread.
// tanh softclamp bounds scores to [-50,50] -> fixed max (p = exp(s-50)),
// single-pass softmax accumulation.
// ---------------------------------------------------------------------------
__global__ __launch_bounds__(128) void attn_kernel()
{
    __shared__ __align__(16) float Ks[64][64];
    __shared__ __align__(16) float Vs[64][64];

    const int tid  = threadIdx.x;
    const int qtok = blockIdx.x * 128 + tid;
    const int h    = blockIdx.y;
    const int bi   = blockIdx.z;

    const size_t head_base = (size_t)(bi * Hc + h) * NTc * Dc;
    const float* qp = g_q + head_base + (size_t)qtok * Dc;

    float4 q[16];
#pragma unroll
    for (int i = 0; i < 16; i++) q[i] = *(const float4*)(qp + i * 4);

    float4 o[16];
#pragma unroll
    for (int i = 0; i < 16; i++) o[i] = make_float4(0.f, 0.f, 0.f, 0.f);
    float l = 0.f;

    const float* kbase = g_k + head_base;
    const float* vbase = g_v + head_base;

    for (int t = 0; t < NTc; t += 64) {
        __syncthreads();
#pragma unroll
        for (int li = 0; li < 8; li++) {
            const int lin = li * 128 + tid;
            const int row = lin >> 4;
            const int c4  = (lin & 15) * 4;
            *(float4*)&Ks[row][c4] = *(const float4*)(kbase + (size_t)(t + row) * Dc + c4);
            *(float4*)&Vs[row][c4] = *(const float4*)(vbase + (size_t)(t + row) * Dc + c4);
        }
        __syncthreads();

#pragma unroll 2
        for (int j = 0; j < 64; j++) {
            float s = 0.f;
#pragma unroll
            for (int i = 0; i < 16; i++) {
                float4 kv = *(const float4*)&Ks[j][i * 4];
                s += q[i].x * kv.x + q[i].y * kv.y + q[i].z * kv.z + q[i].w * kv.w;
            }
            s *= 0.125f;                       // D^-0.5
            s = tanhf(s * (1.0f / 50.0f)) * 50.0f;
            const float p = __expf(s - 50.0f);
            l += p;
#pragma unroll
            for (int i = 0; i < 16; i++) {
                float4 vv = *(const float4*)&Vs[j][i * 4];
                o[i].x += p * vv.x; o[i].y += p * vv.y;
                o[i].z += p * vv.z; o[i].w += p * vv.w;
            }
        }
    }

    const float inv = 1.0f / l;
    float* op = g_o + ((size_t)bi * NTc + qtok) * DIc + h * Dc;
#pragma unroll
    for (int i = 0; i < 16; i++) {
        float4 w = o[i];
        w.x *= inv; w.y *= inv; w.z *= inv; w.w *= inv;
        *(float4*)(op + i * 4) = w;
    }
}

// ---------------------------------------------------------------------------
// Out proj: out[M,Nn] = gather_rows(g_o)[M,1024] @ Wout[1024,Nn]
// ---------------------------------------------------------------------------
__global__ __launch_bounds__(256) void out_gemm(
    const float* __restrict__ Wout, float* __restrict__ out,
    int Nn, int n_m, int mod)
{
    __shared__ __align__(16) float As[8][132];
    __shared__ __align__(16) float Bs[8][128];

    const int tid = threadIdx.x;
    const int bx = blockIdx.x, by = blockIdx.y;
    const int tx = tid & 15, ty = tid >> 4;

    float acc[8][8];
#pragma unroll
    for (int i = 0; i < 8; i++)
#pragma unroll
        for (int j = 0; j < 8; j++) acc[i][j] = 0.f;

    const int aRow = tid >> 1, aCol = (tid & 1) * 4;
    const int bRow = tid >> 5, bCol = (tid & 31) * 4;
    {
        // row map: r -> (bi, t) -> g_o row bi*NT + (mod? N0+t : t)
        const int r  = by * 128 + aRow;
        const int bi = (r >= n_m) ? 1 : 0;
        const int t  = r - bi * n_m;
        const int ar = bi * NTc + (mod ? N0c + t : t);
        const float* Aptr = g_o + (size_t)ar * DIc + aCol;
        const float* Bptr = Wout + (size_t)bRow * Nn + bx * 128 + bCol;

        for (int kk = 0; kk < DIc; kk += 8) {
            float4 av = *(const float4*)(Aptr + kk);
            float4 bv = *(const float4*)(Bptr + (size_t)kk * Nn);
            As[aCol + 0][aRow] = av.x;
            As[aCol + 1][aRow] = av.y;
            As[aCol + 2][aRow] = av.z;
            As[aCol + 3][aRow] = av.w;
            *(float4*)&Bs[bRow][bCol] = bv;
            __syncthreads();
#pragma unroll
            for (int k = 0; k < 8; k++) {
                float a[8], b[8];
                *(float4*)&a[0] = *(const float4*)&As[k][ty * 8];
                *(float4*)&a[4] = *(const float4*)&As[k][ty * 8 + 4];
                *(float4*)&b[0] = *(const float4*)&Bs[k][tx * 8];
                *(float4*)&b[4] = *(const float4*)&Bs[k][tx * 8 + 4];
#pragma unroll
                for (int i = 0; i < 8; i++)
#pragma unroll
                    for (int j = 0; j < 8; j++) acc[i][j] += a[i] * b[j];
            }
            __syncthreads();
        }
    }

    const int c0 = bx * 128 + tx * 8;
#pragma unroll
    for (int i = 0; i < 8; i++) {
        const int r = by * 128 + ty * 8 + i;
        float* p = out + (size_t)r * Nn + c0;
        *(float4*)p       = make_float4(acc[i][0], acc[i][1], acc[i][2], acc[i][3]);
        *(float4*)(p + 4) = make_float4(acc[i][4], acc[i][5], acc[i][6], acc[i][7]);
    }
}

// ---------------------------------------------------------------------------
// Launch
// ---------------------------------------------------------------------------
extern "C" void kernel_launch(void* const* d_in, const int* in_sizes, int n_in,
                              void* d_out, int out_size)
{
    const float* x0    = (const float*)d_in[0];
    const float* x1    = (const float*)d_in[1];
    const float* Wqkv0 = (const float*)d_in[2];
    const float* Wqkv1 = (const float*)d_in[3];
    const float* qg0   = (const float*)d_in[4];
    const float* kg0   = (const float*)d_in[5];
    const float* qg1   = (const float*)d_in[6];
    const float* kg1   = (const float*)d_in[7];
    const float* Wout0 = (const float*)d_in[8];
    const float* Wout1 = (const float*)d_in[9];
    float* out = (float*)d_out;

    // 1) QKV GEMMs (fill g_q/g_k/g_v, disjoint token ranges)
    qkv_gemm<<<dim3(3072 / 128, (BB * N0c) / 128), 256>>>(x0, Wqkv0, D0c, N0c, 0);
    qkv_gemm<<<dim3(3072 / 128, (BB * N1c) / 128), 256>>>(x1, Wqkv1, D1c, N1c, 1);

    // 2) QK RMSNorm (one warp per 64-elem row)
    {
        const int rows = BB * Hc * NTc;          // 65536
        const int blocks = rows / 8;             // 256 thr = 8 warps
        qk_rmsnorm<<<blocks, 256>>>(qg0, kg0, qg1, kg1);
    }

    // 3) Attention -> g_o merged-head layout
    attn_kernel<<<dim3(NTc / 128, Hc, BB), 128>>>();

    // 4) Output projections
    out_gemm<<<dim3(D0c / 128, (BB * N0c) / 128), 256>>>(Wout0, out, D0c, N0c, 0);
    out_gemm<<<dim3(D1c / 128, (BB * N1c) / 128), 256>>>(
        Wout1, out + (size_t)BB * N0c * D0c, D1c, N1c, 1);
}

// round 2
// speedup vs baseline: 3.4686x; 3.4686x over previous
#include <cuda_runtime.h>
#include <math.h>
#include <stdint.h>

// Problem constants
#define BB   2
#define N0c  1536
#define N1c  512
#define NTc  2048          // N0 + N1
#define Hc   16
#define Dc   64            // head dim
#define DIc  1024          // H * D
#define D0c  1024
#define D1c  512

// Scratch (device globals: allocation-free)
__device__ float g_q[BB * Hc * NTc * Dc];   // [b,h,N,D]
__device__ float g_k[BB * Hc * NTc * Dc];
__device__ float g_v[BB * Hc * NTc * Dc];
__device__ float g_o[BB * NTc * DIc];       // [b,N,H*D] merged heads

// ---------------------------------------------------------------------------
// tf32 helpers
// ---------------------------------------------------------------------------
__device__ __forceinline__ uint32_t f2tf(float x) {
    uint32_t r;
    asm("cvt.rna.tf32.f32 %0, %1;" : "=r"(r) : "f"(x));
    return r;
}

__device__ __forceinline__ void mma8(float* c, const uint32_t* a, const uint32_t* b) {
    asm volatile(
        "mma.sync.aligned.m16n8k8.row.col.f32.tf32.tf32.f32 "
        "{%0,%1,%2,%3}, {%4,%5,%6,%7}, {%8,%9}, {%0,%1,%2,%3};\n"
        : "+f"(c[0]), "+f"(c[1]), "+f"(c[2]), "+f"(c[3])
        : "r"(a[0]), "r"(a[1]), "r"(a[2]), "r"(a[3]), "r"(b[0]), "r"(b[1]));
}

__device__ __forceinline__ uint4 cvt4(float4 v) {
    uint4 u;
    u.x = f2tf(v.x); u.y = f2tf(v.y); u.z = f2tf(v.z); u.w = f2tf(v.w);
    return u;
}

// ---------------------------------------------------------------------------
// QKV GEMM (tf32 mma): QKV[M,3072] = X[M,K] @ W[K,3072]
// BM=128 BN=128 BK=16, 256 threads, warp tile 64x32 (wm in {0,1}, wn in {0..3})
// Epilogue scatters into g_q/g_k/g_v [b,h,NT,D]
// ---------------------------------------------------------------------------
#define APAD 20    // 4*gr + ct -> distinct banks
#define BPAD 136   // 8*ct + gr -> distinct banks

__global__ __launch_bounds__(256, 2) void qkv_gemm_t(
    const float* __restrict__ X, const float* __restrict__ W,
    int K, int n_m, int modoff)
{
    __shared__ uint32_t As[128 * APAD];
    __shared__ uint32_t Bs[16 * BPAD];

    const int tid = threadIdx.x;
    const int bx = blockIdx.x, by = blockIdx.y;
    const int warp = tid >> 5, lane = tid & 31;
    const int wm = warp >> 2, wn = warp & 3;
    const int gr = lane >> 2, ct = lane & 3;

    float c[4][4][4];
#pragma unroll
    for (int i = 0; i < 4; i++)
#pragma unroll
        for (int j = 0; j < 4; j++)
#pragma unroll
            for (int k = 0; k < 4; k++) c[i][j][k] = 0.f;

    // A tile 128x16: 512 float4, 2 per thread
    const int aRow0 = tid >> 2,        aK0 = (tid & 3) * 4;
    const int aRow1 = (tid >> 2) + 64, aK1 = aK0;
    const float* Ap0 = X + (size_t)(by * 128 + aRow0) * K + aK0;
    const float* Ap1 = X + (size_t)(by * 128 + aRow1) * K + aK1;
    // B tile 16x128: 512 float4, 2 per thread
    const int bK0 = tid >> 5,       bN = (tid & 31) * 4;
    const int bK1 = (tid >> 5) + 8;
    const float* Bp0 = W + (size_t)bK0 * 3072 + bx * 128 + bN;
    const float* Bp1 = W + (size_t)bK1 * 3072 + bx * 128 + bN;

    const int niter = K >> 4;
    float4 ar0 = *(const float4*)Ap0;
    float4 ar1 = *(const float4*)Ap1;
    float4 br0 = *(const float4*)Bp0;
    float4 br1 = *(const float4*)Bp1;

    for (int it = 0; it < niter; ++it) {
        __syncthreads();
        *(uint4*)(As + aRow0 * APAD + aK0) = cvt4(ar0);
        *(uint4*)(As + aRow1 * APAD + aK1) = cvt4(ar1);
        *(uint4*)(Bs + bK0 * BPAD + bN)    = cvt4(br0);
        *(uint4*)(Bs + bK1 * BPAD + bN)    = cvt4(br1);
        __syncthreads();
        if (it + 1 < niter) {
            const int o = (it + 1) * 16;
            ar0 = *(const float4*)(Ap0 + o);
            ar1 = *(const float4*)(Ap1 + o);
            br0 = *(const float4*)(Bp0 + (size_t)o * 3072);
            br1 = *(const float4*)(Bp1 + (size_t)o * 3072);
        }
#pragma unroll
        for (int kc = 0; kc < 2; kc++) {
            uint32_t a[4][4], b[4][2];
#pragma unroll
            for (int i = 0; i < 4; i++) {
                const int r = wm * 64 + i * 16 + gr;
                a[i][0] = As[r * APAD + kc * 8 + ct];
                a[i][1] = As[(r + 8) * APAD + kc * 8 + ct];
                a[i][2] = As[r * APAD + kc * 8 + ct + 4];
                a[i][3] = As[(r + 8) * APAD + kc * 8 + ct + 4];
            }
#pragma unroll
            for (int j = 0; j < 4; j++) {
                const int n = wn * 32 + j * 8 + gr;
                b[j][0] = Bs[(kc * 8 + ct) * BPAD + n];
                b[j][1] = Bs[(kc * 8 + ct + 4) * BPAD + n];
            }
#pragma unroll
            for (int i = 0; i < 4; i++)
#pragma unroll
                for (int j = 0; j < 4; j++) mma8(c[i][j], a[i], b[j]);
        }
    }

    // Epilogue: scatter into q/k/v
#pragma unroll
    for (int j = 0; j < 4; j++) {
        const int gc = bx * 128 + wn * 32 + j * 8 + 2 * ct;
        const int qkvI = gc >> 10;
        const int hh = (gc >> 6) & (Hc - 1);
        const int dd = gc & (Dc - 1);
        float* dst = (qkvI == 0) ? g_q : ((qkvI == 1) ? g_k : g_v);
#pragma unroll
        for (int i = 0; i < 4; i++) {
            const int r = by * 128 + wm * 64 + i * 16 + gr;
            {
                const int bi2 = (r >= n_m) ? 1 : 0;
                const int tok = r - bi2 * n_m + modoff;
                float2 v = make_float2(c[i][j][0], c[i][j][1]);
                *(float2*)(dst + ((size_t)(bi2 * Hc + hh) * NTc + tok) * Dc + dd) = v;
            }
            {
                const int r2 = r + 8;
                const int bi2 = (r2 >= n_m) ? 1 : 0;
                const int tok = r2 - bi2 * n_m + modoff;
                float2 v = make_float2(c[i][j][2], c[i][j][3]);
                *(float2*)(dst + ((size_t)(bi2 * Hc + hh) * NTc + tok) * Dc + dd) = v;
            }
        }
    }
}

// ---------------------------------------------------------------------------
// QK RMSNorm (unchanged, fp32)
// ---------------------------------------------------------------------------
__global__ __launch_bounds__(256) void qk_rmsnorm(
    const float* __restrict__ qg0, const float* __restrict__ kg0,
    const float* __restrict__ qg1, const float* __restrict__ kg1)
{
    const int warp = (blockIdx.x * blockDim.x + threadIdx.x) >> 5;
    const int lane = threadIdx.x & 31;
    if (warp >= BB * Hc * NTc) return;

    const int h   = (warp >> 11) & (Hc - 1);
    const int tok = warp & (NTc - 1);
    const int mod = (tok >= N0c) ? 1 : 0;
    const float* qg = mod ? qg1 : qg0;
    const float* kg = mod ? kg1 : kg0;
    const float gq0 = qg[h * 64 + lane], gq1 = qg[h * 64 + lane + 32];
    const float gk0 = kg[h * 64 + lane], gk1 = kg[h * 64 + lane + 32];

    {
        float* p = g_q + (size_t)warp * 64;
        float a = p[lane], b = p[lane + 32];
        float ss = a * a + b * b;
#pragma unroll
        for (int off = 16; off > 0; off >>= 1)
            ss += __shfl_xor_sync(0xFFFFFFFFu, ss, off);
        float s = 8.0f / fmaxf(sqrtf(ss), 1e-12f);
        p[lane]      = a * s * gq0;
        p[lane + 32] = b * s * gq1;
    }
    {
        float* p = g_k + (size_t)warp * 64;
        float a = p[lane], b = p[lane + 32];
        float ss = a * a + b * b;
#pragma unroll
        for (int off = 16; off > 0; off >>= 1)
            ss += __shfl_xor_sync(0xFFFFFFFFu, ss, off);
        float s = 8.0f / fmaxf(sqrtf(ss), 1e-12f);
        p[lane]      = a * s * gk0;
        p[lane + 32] = b * s * gk1;
    }
}

// ---------------------------------------------------------------------------
// Attention (tf32 mma): grid (16, H, B), 256 threads = 8 warps, 16 q-rows/warp.
// Softclamp: p = exp(50 - 100/(e+1)), e = exp(0.005 * rawdot); fixed-max softmax.
// ---------------------------------------------------------------------------
#define KPAD 68   // key-row-indexed-by-gr frag reads: banks 4*gr+ct distinct
#define VPAD 72   // key-row-indexed-by-ct frag reads: banks 8*ct+gr distinct

__device__ __forceinline__ float softclamp_p(float craw) {
    const float e = __expf(craw * 0.005f);
    return __expf(50.0f - __fdividef(100.0f, e + 1.0f));
}

__global__ __launch_bounds__(256) void attn_t()
{
    __shared__ uint32_t sm[64 * KPAD + 64 * VPAD];   // 8960 u32 = 35 KB
    uint32_t* Ks = sm;
    uint32_t* Vs = sm + 64 * KPAD;

    const int tid  = threadIdx.x;
    const int warp = tid >> 5, lane = tid & 31;
    const int gr = lane >> 2, ct = lane & 3;
    const int h  = blockIdx.y, bi = blockIdx.z;

    const size_t hb = (size_t)(bi * Hc + h) * NTc * Dc;
    const float* qp = g_q + hb + (size_t)blockIdx.x * 128 * Dc;

    // Stage Q tile (128x64) into smem (tf32 bits), then build A-frags.
    uint32_t* qs = sm;   // [128][68] = 8704 u32, aliases Ks+Vs
#pragma unroll
    for (int i = 0; i < 8; i++) {
        const int f = i * 256 + tid;
        const int row = f >> 4, c4 = (f & 15) * 4;
        float4 v = *(const float4*)(qp + row * Dc + c4);
        *(uint4*)(qs + row * KPAD + c4) = cvt4(v);
    }
    __syncthreads();

    uint32_t qa[8][4];
    {
        const int r0 = warp * 16 + gr;
#pragma unroll
        for (int kc = 0; kc < 8; kc++) {
            qa[kc][0] = qs[r0 * KPAD + kc * 8 + ct];
            qa[kc][1] = qs[(r0 + 8) * KPAD + kc * 8 + ct];
            qa[kc][2] = qs[r0 * KPAD + kc * 8 + ct + 4];
            qa[kc][3] = qs[(r0 + 8) * KPAD + kc * 8 + ct + 4];
        }
    }
    __syncthreads();

    float oc[8][4];
#pragma unroll
    for (int n = 0; n < 8; n++)
#pragma unroll
        for (int k = 0; k < 4; k++) oc[n][k] = 0.f;
    float l0 = 0.f, l1 = 0.f;

    const float* kb = g_k + hb;
    const float* vb = g_v + hb;

    for (int t = 0; t < NTc / 64; t++) {
        // Load K,V tile (64x64 each), cvt to tf32 at store
#pragma unroll
        for (int i = 0; i < 4; i++) {
            const int f = i * 256 + tid;
            const int row = f >> 4, c4 = (f & 15) * 4;
            float4 kv = *(const float4*)(kb + (size_t)(t * 64 + row) * Dc + c4);
            float4 vv = *(const float4*)(vb + (size_t)(t * 64 + row) * Dc + c4);
            *(uint4*)(Ks + row * KPAD + c4) = cvt4(kv);
            *(uint4*)(Vs + row * VPAD + c4) = cvt4(vv);
        }
        __syncthreads();

        // S = Q @ K^T  (16 x 64 per warp)
        float s[8][4];
#pragma unroll
        for (int j = 0; j < 8; j++)
#pragma unroll
            for (int k = 0; k < 4; k++) s[j][k] = 0.f;

#pragma unroll
        for (int kc = 0; kc < 8; kc++) {
#pragma unroll
            for (int j = 0; j < 8; j++) {
                uint32_t b[2];
                b[0] = Ks[(j * 8 + gr) * KPAD + kc * 8 + ct];
                b[1] = Ks[(j * 8 + gr) * KPAD + kc * 8 + ct + 4];
                mma8(s[j], qa[kc], b);
            }
        }

        // Softmax (fixed max) + P remap (C-frag -> A-frag) + PV
        const unsigned base = lane & ~3u;
        const int half = ct >> 1, odd = ct & 1;
#pragma unroll
        for (int j = 0; j < 8; j++) {
            const float p0 = softclamp_p(s[j][0]);
            const float p1 = softclamp_p(s[j][1]);
            const float p2 = softclamp_p(s[j][2]);
            const float p3 = softclamp_p(s[j][3]);
            l0 += p0 + p1;
            l1 += p2 + p3;

            const float t0 = __shfl_sync(0xFFFFFFFFu, p0, base + half);
            const float t1 = __shfl_sync(0xFFFFFFFFu, p1, base + half);
            const float u0 = __shfl_sync(0xFFFFFFFFu, p0, base + half + 2);
            const float u1 = __shfl_sync(0xFFFFFFFFu, p1, base + half + 2);
            const float r0 = __shfl_sync(0xFFFFFFFFu, p2, base + half);
            const float r1 = __shfl_sync(0xFFFFFFFFu, p3, base + half);
            const float w0 = __shfl_sync(0xFFFFFFFFu, p2, base + half + 2);
            const float w1 = __shfl_sync(0xFFFFFFFFu, p3, base + half + 2);

            uint32_t pa[4];
            pa[0] = f2tf(odd ? t1 : t0);
            pa[1] = f2tf(odd ? r1 : r0);
            pa[2] = f2tf(odd ? u1 : u0);
            pa[3] = f2tf(odd ? w1 : w0);

#pragma unroll
            for (int n = 0; n < 8; n++) {
                uint32_t b[2];
                b[0] = Vs[(j * 8 + ct) * VPAD + n * 8 + gr];
                b[1] = Vs[(j * 8 + ct + 4) * VPAD + n * 8 + gr];
                mma8(oc[n], pa, b);
            }
        }
        __syncthreads();
    }

    // Row-sum reduce across the 4 lanes of each group, then normalize + store
    l0 += __shfl_xor_sync(0xFFFFFFFFu, l0, 1);
    l0 += __shfl_xor_sync(0xFFFFFFFFu, l0, 2);
    l1 += __shfl_xor_sync(0xFFFFFFFFu, l1, 1);
    l1 += __shfl_xor_sync(0xFFFFFFFFu, l1, 2);
    const float inv0 = 1.0f / l0;
    const float inv1 = 1.0f / l1;

    const int qrow0 = blockIdx.x * 128 + warp * 16 + gr;
    float* op0 = g_o + ((size_t)bi * NTc + qrow0) * DIc + h * Dc;
    float* op1 = op0 + 8 * DIc;
#pragma unroll
    for (int n = 0; n < 8; n++) {
        const int col = n * 8 + 2 * ct;
        *(float2*)(op0 + col) = make_float2(oc[n][0] * inv0, oc[n][1] * inv0);
        *(float2*)(op1 + col) = make_float2(oc[n][2] * inv1, oc[n][3] * inv1);
    }
}

// ---------------------------------------------------------------------------
// Out proj (tf32 mma): out[M,Nn] = gather_rows(g_o)[M,1024] @ Wout[1024,Nn]
// ---------------------------------------------------------------------------
__global__ __launch_bounds__(256, 2) void out_gemm_t(
    const float* __restrict__ Wout, float* __restrict__ out,
    int Nn, int n_m, int modoff)
{
    __shared__ uint32_t As[128 * APAD];
    __shared__ uint32_t Bs[16 * BPAD];

    const int tid = threadIdx.x;
    const int bx = blockIdx.x, by = blockIdx.y;
    const int warp = tid >> 5, lane = tid & 31;
    const int wm = warp >> 2, wn = warp & 3;
    const int gr = lane >> 2, ct = lane & 3;

    float c[4][4][4];
#pragma unroll
    for (int i = 0; i < 4; i++)
#pragma unroll
        for (int j = 0; j < 4; j++)
#pragma unroll
            for (int k = 0; k < 4; k++) c[i][j][k] = 0.f;

    const int aRow0 = tid >> 2,        aK0 = (tid & 3) * 4;
    const int aRow1 = (tid >> 2) + 64, aK1 = aK0;
    // Gather g_o rows (modality-interleaved token order)
    const float* Ap0; const float* Ap1;
    {
        const int r = by * 128 + aRow0;
        const int bi2 = (r >= n_m) ? 1 : 0;
        Ap0 = g_o + ((size_t)bi2 * NTc + (r - bi2 * n_m) + modoff) * DIc + aK0;
    }
    {
        const int r = by * 128 + aRow1;
        const int bi2 = (r >= n_m) ? 1 : 0;
        Ap1 = g_o + ((size_t)bi2 * NTc + (r - bi2 * n_m) + modoff) * DIc + aK1;
    }
    const int bK0 = tid >> 5,       bN = (tid & 31) * 4;
    const int bK1 = (tid >> 5) + 8;
    const float* Bp0 = Wout + (size_t)bK0 * Nn + bx * 128 + bN;
    const float* Bp1 = Wout + (size_t)bK1 * Nn + bx * 128 + bN;

    const int niter = DIc >> 4;   // 64
    float4 ar0 = *(const float4*)Ap0;
    float4 ar1 = *(const float4*)Ap1;
    float4 br0 = *(const float4*)Bp0;
    float4 br1 = *(const float4*)Bp1;

    for (int it = 0; it < niter; ++it) {
        __syncthreads();
        *(uint4*)(As + aRow0 * APAD + aK0) = cvt4(ar0);
        *(uint4*)(As + aRow1 * APAD + aK1) = cvt4(ar1);
        *(uint4*)(Bs + bK0 * BPAD + bN)    = cvt4(br0);
        *(uint4*)(Bs + bK1 * BPAD + bN)    = cvt4(br1);
        __syncthreads();
        if (it + 1 < niter) {
            const int o = (it + 1) * 16;
            ar0 = *(const float4*)(Ap0 + o);
            ar1 = *(const float4*)(Ap1 + o);
            br0 = *(const float4*)(Bp0 + (size_t)o * Nn);
            br1 = *(const float4*)(Bp1 + (size_t)o * Nn);
        }
#pragma unroll
        for (int kc = 0; kc < 2; kc++) {
            uint32_t a[4][4], b[4][2];
#pragma unroll
            for (int i = 0; i < 4; i++) {
                const int r = wm * 64 + i * 16 + gr;
                a[i][0] = As[r * APAD + kc * 8 + ct];
                a[i][1] = As[(r + 8) * APAD + kc * 8 + ct];
                a[i][2] = As[r * APAD + kc * 8 + ct + 4];
                a[i][3] = As[(r + 8) * APAD + kc * 8 + ct + 4];
            }
#pragma unroll
            for (int j = 0; j < 4; j++) {
                const int n = wn * 32 + j * 8 + gr;
                b[j][0] = Bs[(kc * 8 + ct) * BPAD + n];
                b[j][1] = Bs[(kc * 8 + ct + 4) * BPAD + n];
            }
#pragma unroll
            for (int i = 0; i < 4; i++)
#pragma unroll
                for (int j = 0; j < 4; j++) mma8(c[i][j], a[i], b[j]);
        }
    }

#pragma unroll
    for (int j = 0; j < 4; j++) {
        const int col = bx * 128 + wn * 32 + j * 8 + 2 * ct;
#pragma unroll
        for (int i = 0; i < 4; i++) {
            const int r = by * 128 + wm * 64 + i * 16 + gr;
            *(float2*)(out + (size_t)r * Nn + col) =
                make_float2(c[i][j][0], c[i][j][1]);
            *(float2*)(out + (size_t)(r + 8) * Nn + col) =
                make_float2(c[i][j][2], c[i][j][3]);
        }
    }
}

// ---------------------------------------------------------------------------
// Launch
// ---------------------------------------------------------------------------
extern "C" void kernel_launch(void* const* d_in, const int* in_sizes, int n_in,
                              void* d_out, int out_size)
{
    const float* x0    = (const float*)d_in[0];
    const float* x1    = (const float*)d_in[1];
    const float* Wqkv0 = (const float*)d_in[2];
    const float* Wqkv1 = (const float*)d_in[3];
    const float* qg0   = (const float*)d_in[4];
    const float* kg0   = (const float*)d_in[5];
    const float* qg1   = (const float*)d_in[6];
    const float* kg1   = (const float*)d_in[7];
    const float* Wout0 = (const float*)d_in[8];
    const float* Wout1 = (const float*)d_in[9];
    float* out = (float*)d_out;

    // 1) QKV GEMMs (tensor cores, tf32)
    qkv_gemm_t<<<dim3(3072 / 128, (BB * N0c) / 128), 256>>>(x0, Wqkv0, D0c, N0c, 0);
    qkv_gemm_t<<<dim3(3072 / 128, (BB * N1c) / 128), 256>>>(x1, Wqkv1, D1c, N1c, N0c);

    // 2) QK RMSNorm
    {
        const int rows = BB * Hc * NTc;
        qk_rmsnorm<<<rows / 8, 256>>>(qg0, kg0, qg1, kg1);
    }

    // 3) Attention (tensor cores, tf32)
    attn_t<<<dim3(NTc / 128, Hc, BB), 256>>>();

    // 4) Output projections (tensor cores, tf32)
    out_gemm_t<<<dim3(D0c / 128, (BB * N0c) / 128), 256>>>(Wout0, out, D0c, N0c, 0);
    out_gemm_t<<<dim3(D1c / 128, (BB * N1c) / 128), 256>>>(
        Wout1, out + (size_t)BB * N0c * D0c, D1c, N1c, N0c);
}

// round 3
// speedup vs baseline: 4.2843x; 1.2352x over previous
#include <cuda_runtime.h>
#include <math.h>
#include <stdint.h>

// Problem constants
#define BB   2
#define N0c  1536
#define N1c  512
#define NTc  2048          // N0 + N1
#define Hc   16
#define Dc   64            // head dim
#define DIc  1024          // H * D
#define D0c  1024
#define D1c  512

// Scratch (device globals: allocation-free)
__device__ float g_q[BB * Hc * NTc * Dc];   // [b,h,N,D]
__device__ float g_k[BB * Hc * NTc * Dc];
__device__ float g_v[BB * Hc * NTc * Dc];
__device__ float g_o[BB * NTc * DIc];       // [b,N,H*D] merged heads

// ---------------------------------------------------------------------------
// tf32 helpers
// ---------------------------------------------------------------------------
__device__ __forceinline__ uint32_t f2tf(float x) {
    uint32_t r;
    asm("cvt.rna.tf32.f32 %0, %1;" : "=r"(r) : "f"(x));
    return r;
}

__device__ __forceinline__ void mma8(float* c, const uint32_t* a, const uint32_t* b) {
    asm volatile(
        "mma.sync.aligned.m16n8k8.row.col.f32.tf32.tf32.f32 "
        "{%0,%1,%2,%3}, {%4,%5,%6,%7}, {%8,%9}, {%0,%1,%2,%3};\n"
        : "+f"(c[0]), "+f"(c[1]), "+f"(c[2]), "+f"(c[3])
        : "r"(a[0]), "r"(a[1]), "r"(a[2]), "r"(a[3]), "r"(b[0]), "r"(b[1]));
}

__device__ __forceinline__ uint4 cvt4(float4 v) {
    uint4 u;
    u.x = f2tf(v.x); u.y = f2tf(v.y); u.z = f2tf(v.z); u.w = f2tf(v.w);
    return u;
}

// softclamp+exp: p = exp(50*tanh(score/50)), score = dot/8, |score|<=8 exactly
// (post-RMSNorm rows have norm 8). tanh on |x|<=0.16 via 3-term odd poly,
// folded with log2(e): p = ex2(sc*(c0 + u*c1 + u^2*c2)), u = sc^2.
__device__ __forceinline__ float sc_p(float dot) {
    const float sc = dot * 0.125f;
    const float u = sc * sc;
    const float t = sc * fmaf(u, fmaf(u, 3.0777494e-8f, -1.9235934e-4f), 1.4426950f);
    float p;
    asm("ex2.approx.f32 %0, %1;" : "=f"(p) : "f"(t));
    return p;
}

// ---------------------------------------------------------------------------
// Fused QKV GEMM (tf32 mma, double-buffered): QKV[M,3072] = X[M,K] @ W[K,3072]
// grid (24, 32): by<24 -> modality 0 (K=1024), else modality 1 (K=512)
// BM=128 BN=128 BK=16, 256 threads, warp tile 64x32
// ---------------------------------------------------------------------------
#define APAD 20    // 4*gr + ct -> distinct banks
#define BPAD 136   // 8*ct + gr -> distinct banks

__global__ __launch_bounds__(256, 2) void qkv_gemm_t(
    const float* __restrict__ x0, const float* __restrict__ x1,
    const float* __restrict__ W0, const float* __restrict__ W1)
{
    __shared__ uint32_t As[2][128 * APAD];
    __shared__ uint32_t Bs[2][16 * BPAD];

    const float* X; const float* W; int K, n_m, modoff, yb;
    if (blockIdx.y < 24) { X = x0; W = W0; K = D0c; n_m = N0c; modoff = 0;   yb = blockIdx.y; }
    else                 { X = x1; W = W1; K = D1c; n_m = N1c; modoff = N0c; yb = blockIdx.y - 24; }

    const int tid = threadIdx.x;
    const int bx = blockIdx.x;
    const int warp = tid >> 5, lane = tid & 31;
    const int wm = warp >> 2, wn = warp & 3;
    const int gr = lane >> 2, ct = lane & 3;

    float c[4][4][4];
#pragma unroll
    for (int i = 0; i < 4; i++)
#pragma unroll
        for (int j = 0; j < 4; j++)
#pragma unroll
            for (int k = 0; k < 4; k++) c[i][j][k] = 0.f;

    const int aRow0 = tid >> 2,        aK0 = (tid & 3) * 4;
    const int aRow1 = (tid >> 2) + 64;
    const int bK0 = tid >> 5,          bN = (tid & 31) * 4;
    const int bK1 = (tid >> 5) + 8;
    const float* Ap0 = X + (size_t)(yb * 128 + aRow0) * K + aK0;
    const float* Ap1 = X + (size_t)(yb * 128 + aRow1) * K + aK0;
    const float* Bp0 = W + (size_t)bK0 * 3072 + bx * 128 + bN;
    const float* Bp1 = W + (size_t)bK1 * 3072 + bx * 128 + bN;

    const int niter = K >> 4;
    float4 ar0 = *(const float4*)Ap0;
    float4 ar1 = *(const float4*)Ap1;
    float4 br0 = *(const float4*)Bp0;
    float4 br1 = *(const float4*)Bp1;

    *(uint4*)(&As[0][aRow0 * APAD + aK0]) = cvt4(ar0);
    *(uint4*)(&As[0][aRow1 * APAD + aK0]) = cvt4(ar1);
    *(uint4*)(&Bs[0][bK0 * BPAD + bN])    = cvt4(br0);
    *(uint4*)(&Bs[0][bK1 * BPAD + bN])    = cvt4(br1);
    __syncthreads();

    for (int it = 0; it < niter; ++it) {
        const int cur = it & 1;
        const bool more = (it + 1 < niter);
        if (more) {
            const int o = (it + 1) * 16;
            ar0 = *(const float4*)(Ap0 + o);
            ar1 = *(const float4*)(Ap1 + o);
            br0 = *(const float4*)(Bp0 + (size_t)o * 3072);
            br1 = *(const float4*)(Bp1 + (size_t)o * 3072);
        }
        const uint32_t* Ac = As[cur];
        const uint32_t* Bc = Bs[cur];
#pragma unroll
        for (int kc = 0; kc < 2; kc++) {
            uint32_t a[4][4], b[4][2];
#pragma unroll
            for (int i = 0; i < 4; i++) {
                const int r = wm * 64 + i * 16 + gr;
                a[i][0] = Ac[r * APAD + kc * 8 + ct];
                a[i][1] = Ac[(r + 8) * APAD + kc * 8 + ct];
                a[i][2] = Ac[r * APAD + kc * 8 + ct + 4];
                a[i][3] = Ac[(r + 8) * APAD + kc * 8 + ct + 4];
            }
#pragma unroll
            for (int j = 0; j < 4; j++) {
                const int n = wn * 32 + j * 8 + gr;
                b[j][0] = Bc[(kc * 8 + ct) * BPAD + n];
                b[j][1] = Bc[(kc * 8 + ct + 4) * BPAD + n];
            }
#pragma unroll
            for (int i = 0; i < 4; i++)
#pragma unroll
                for (int j = 0; j < 4; j++) mma8(c[i][j], a[i], b[j]);
        }
        if (more) {
            const int nxt = cur ^ 1;
            *(uint4*)(&As[nxt][aRow0 * APAD + aK0]) = cvt4(ar0);
            *(uint4*)(&As[nxt][aRow1 * APAD + aK0]) = cvt4(ar1);
            *(uint4*)(&Bs[nxt][bK0 * BPAD + bN])    = cvt4(br0);
            *(uint4*)(&Bs[nxt][bK1 * BPAD + bN])    = cvt4(br1);
            __syncthreads();
        }
    }

    // Epilogue: scatter into q/k/v [b,h,NT,D]
#pragma unroll
    for (int j = 0; j < 4; j++) {
        const int gc = bx * 128 + wn * 32 + j * 8 + 2 * ct;
        const int qkvI = gc >> 10;
        const int hh = (gc >> 6) & (Hc - 1);
        const int dd = gc & (Dc - 1);
        float* dst = (qkvI == 0) ? g_q : ((qkvI == 1) ? g_k : g_v);
#pragma unroll
        for (int i = 0; i < 4; i++) {
            const int r = yb * 128 + wm * 64 + i * 16 + gr;
            {
                const int bi2 = (r >= n_m) ? 1 : 0;
                const int tok = r - bi2 * n_m + modoff;
                *(float2*)(dst + ((size_t)(bi2 * Hc + hh) * NTc + tok) * Dc + dd) =
                    make_float2(c[i][j][0], c[i][j][1]);
            }
            {
                const int r2 = r + 8;
                const int bi2 = (r2 >= n_m) ? 1 : 0;
                const int tok = r2 - bi2 * n_m + modoff;
                *(float2*)(dst + ((size_t)(bi2 * Hc + hh) * NTc + tok) * Dc + dd) =
                    make_float2(c[i][j][2], c[i][j][3]);
            }
        }
    }
}

// ---------------------------------------------------------------------------
// QK RMSNorm (fp32)
// ---------------------------------------------------------------------------
__global__ __launch_bounds__(256) void qk_rmsnorm(
    const float* __restrict__ qg0, const float* __restrict__ kg0,
    const float* __restrict__ qg1, const float* __restrict__ kg1)
{
    const int warp = (blockIdx.x * blockDim.x + threadIdx.x) >> 5;
    const int lane = threadIdx.x & 31;
    if (warp >= BB * Hc * NTc) return;

    const int h   = (warp >> 11) & (Hc - 1);
    const int tok = warp & (NTc - 1);
    const int mod = (tok >= N0c) ? 1 : 0;
    const float* qg = mod ? qg1 : qg0;
    const float* kg = mod ? kg1 : kg0;
    const float gq0 = qg[h * 64 + lane], gq1 = qg[h * 64 + lane + 32];
    const float gk0 = kg[h * 64 + lane], gk1 = kg[h * 64 + lane + 32];

    {
        float* p = g_q + (size_t)warp * 64;
        float a = p[lane], b = p[lane + 32];
        float ss = a * a + b * b;
#pragma unroll
        for (int off = 16; off > 0; off >>= 1)
            ss += __shfl_xor_sync(0xFFFFFFFFu, ss, off);
        float s = 8.0f / fmaxf(sqrtf(ss), 1e-12f);
        p[lane]      = a * s * gq0;
        p[lane + 32] = b * s * gq1;
    }
    {
        float* p = g_k + (size_t)warp * 64;
        float a = p[lane], b = p[lane + 32];
        float ss = a * a + b * b;
#pragma unroll
        for (int off = 16; off > 0; off >>= 1)
            ss += __shfl_xor_sync(0xFFFFFFFFu, ss, off);
        float s = 8.0f / fmaxf(sqrtf(ss), 1e-12f);
        p[lane]      = a * s * gk0;
        p[lane + 32] = b * s * gk1;
    }
}

// ---------------------------------------------------------------------------
// Attention (tf32 mma): grid (16, H, B), 128 threads = 4 warps, 32 q-rows/warp.
// B-fragments (K,V smem reads) are shared across the 2 m-tiles in a warp,
// halving smem traffic per q-row vs 16-row warps.
// ---------------------------------------------------------------------------
#define KPAD 68   // frag reads by gr: banks 4*gr+ct distinct
#define VPAD 72   // frag reads by ct: banks 8*ct+gr distinct

__global__ __launch_bounds__(128) void attn_t()
{
    __shared__ uint32_t sm[64 * KPAD + 64 * VPAD];   // 8960 u32 = 35.8 KB
    uint32_t* Ks = sm;
    uint32_t* Vs = sm + 64 * KPAD;

    const int tid  = threadIdx.x;
    const int warp = tid >> 5, lane = tid & 31;
    const int gr = lane >> 2, ct = lane & 3;
    const int h  = blockIdx.y, bi = blockIdx.z;

    const size_t hb = (size_t)(bi * Hc + h) * NTc * Dc;
    const float* qp = g_q + hb + (size_t)blockIdx.x * 128 * Dc;

    // Stage Q tile (128x64) into smem (tf32), build A-frags (2 m-tiles/warp).
    uint32_t* qs = sm;   // aliases Ks+Vs region
#pragma unroll
    for (int i = 0; i < 16; i++) {
        const int f = i * 128 + tid;
        const int row = f >> 4, c4 = (f & 15) * 4;
        *(uint4*)(qs + row * KPAD + c4) = cvt4(*(const float4*)(qp + row * Dc + c4));
    }
    __syncthreads();

    uint32_t qa[8][2][4];
#pragma unroll
    for (int kc = 0; kc < 8; kc++)
#pragma unroll
        for (int m = 0; m < 2; m++) {
            const int r = warp * 32 + m * 16 + gr;
            qa[kc][m][0] = qs[r * KPAD + kc * 8 + ct];
            qa[kc][m][1] = qs[(r + 8) * KPAD + kc * 8 + ct];
            qa[kc][m][2] = qs[r * KPAD + kc * 8 + ct + 4];
            qa[kc][m][3] = qs[(r + 8) * KPAD + kc * 8 + ct + 4];
        }
    __syncthreads();

    float oc[2][8][4];
#pragma unroll
    for (int m = 0; m < 2; m++)
#pragma unroll
        for (int n = 0; n < 8; n++)
#pragma unroll
            for (int k = 0; k < 4; k++) oc[m][n][k] = 0.f;
    float l[2][2] = {{0.f, 0.f}, {0.f, 0.f}};

    const float* kb = g_k + hb;
    const float* vb = g_v + hb;
    const unsigned base = lane & ~3u;
    const int half = ct >> 1, odd = ct & 1;

    for (int t = 0; t < NTc / 64; t++) {
        // Load K,V tile (64x64 each), cvt to tf32 at store
#pragma unroll
        for (int i = 0; i < 8; i++) {
            const int f = i * 128 + tid;
            const int row = f >> 4, c4 = (f & 15) * 4;
            *(uint4*)(Ks + row * KPAD + c4) =
                cvt4(*(const float4*)(kb + (size_t)(t * 64 + row) * Dc + c4));
            *(uint4*)(Vs + row * VPAD + c4) =
                cvt4(*(const float4*)(vb + (size_t)(t * 64 + row) * Dc + c4));
        }
        __syncthreads();

#pragma unroll
        for (int j = 0; j < 8; j++) {
            // S tile: 32 q-rows x 8 keys
            float s0[4] = {0.f, 0.f, 0.f, 0.f};
            float s1[4] = {0.f, 0.f, 0.f, 0.f};
#pragma unroll
            for (int kc = 0; kc < 8; kc++) {
                uint32_t b[2];
                b[0] = Ks[(j * 8 + gr) * KPAD + kc * 8 + ct];
                b[1] = Ks[(j * 8 + gr) * KPAD + kc * 8 + ct + 4];
                mma8(s0, qa[kc][0], b);
                mma8(s1, qa[kc][1], b);
            }

            // softclamp+exp, l accumulation, C-frag -> A-frag remap
            uint32_t pa[2][4];
#pragma unroll
            for (int m = 0; m < 2; m++) {
                const float* s = m ? s1 : s0;
                const float p0 = sc_p(s[0]);
                const float p1 = sc_p(s[1]);
                const float p2 = sc_p(s[2]);
                const float p3 = sc_p(s[3]);
                l[m][0] += p0 + p1;
                l[m][1] += p2 + p3;

                const float t0 = __shfl_sync(0xFFFFFFFFu, p0, base + half);
                const float t1 = __shfl_sync(0xFFFFFFFFu, p1, base + half);
                const float u0 = __shfl_sync(0xFFFFFFFFu, p0, base + half + 2);
                const float u1 = __shfl_sync(0xFFFFFFFFu, p1, base + half + 2);
                const float r0 = __shfl_sync(0xFFFFFFFFu, p2, base + half);
                const float r1 = __shfl_sync(0xFFFFFFFFu, p3, base + half);
                const float w0 = __shfl_sync(0xFFFFFFFFu, p2, base + half + 2);
                const float w1 = __shfl_sync(0xFFFFFFFFu, p3, base + half + 2);

                pa[m][0] = f2tf(odd ? t1 : t0);
                pa[m][1] = f2tf(odd ? r1 : r0);
                pa[m][2] = f2tf(odd ? u1 : u0);
                pa[m][3] = f2tf(odd ? w1 : w0);
            }

            // PV: vb frags shared across both m-tiles
#pragma unroll
            for (int n = 0; n < 8; n++) {
                uint32_t b[2];
                b[0] = Vs[(j * 8 + ct) * VPAD + n * 8 + gr];
                b[1] = Vs[(j * 8 + ct + 4) * VPAD + n * 8 + gr];
                mma8(oc[0][n], pa[0], b);
                mma8(oc[1][n], pa[1], b);
            }
        }
        __syncthreads();
    }

    // Reduce l across quad lanes, normalize, store
#pragma unroll
    for (int m = 0; m < 2; m++)
#pragma unroll
        for (int rr = 0; rr < 2; rr++) {
            l[m][rr] += __shfl_xor_sync(0xFFFFFFFFu, l[m][rr], 1);
            l[m][rr] += __shfl_xor_sync(0xFFFFFFFFu, l[m][rr], 2);
        }

#pragma unroll
    for (int m = 0; m < 2; m++) {
        const int row = blockIdx.x * 128 + warp * 32 + m * 16 + gr;
        float* op0 = g_o + ((size_t)bi * NTc + row) * DIc + h * Dc;
        float* op1 = op0 + 8 * DIc;
        const float i0 = 1.0f / l[m][0];
        const float i1 = 1.0f / l[m][1];
#pragma unroll
        for (int n = 0; n < 8; n++) {
            const int col = n * 8 + 2 * ct;
            *(float2*)(op0 + col) = make_float2(oc[m][n][0] * i0, oc[m][n][1] * i0);
            *(float2*)(op1 + col) = make_float2(oc[m][n][2] * i1, oc[m][n][3] * i1);
        }
    }
}

// ---------------------------------------------------------------------------
// Fused out proj (tf32 mma, double-buffered):
// out[M,Nn] = gather_rows(g_o)[M,1024] @ Wout[1024,Nn]
// 1D grid, 224 blocks: [0,192) mod0 (8x24), [192,224) mod1 (4x8)
// ---------------------------------------------------------------------------
__global__ __launch_bounds__(256, 2) void out_gemm_t(
    const float* __restrict__ W0, const float* __restrict__ W1,
    float* __restrict__ outp)
{
    __shared__ uint32_t As[2][128 * APAD];
    __shared__ uint32_t Bs[2][16 * BPAD];

    const float* Wout; float* outb; int Nn, n_m, modoff, bx, by;
    if (blockIdx.x < 192) {
        Wout = W0; outb = outp; Nn = D0c; n_m = N0c; modoff = 0;
        bx = blockIdx.x & 7; by = blockIdx.x >> 3;
    } else {
        const int b2 = blockIdx.x - 192;
        Wout = W1; outb = outp + (size_t)BB * N0c * D0c; Nn = D1c; n_m = N1c; modoff = N0c;
        bx = b2 & 3; by = b2 >> 2;
    }

    const int tid = threadIdx.x;
    const int warp = tid >> 5, lane = tid & 31;
    const int wm = warp >> 2, wn = warp & 3;
    const int gr = lane >> 2, ct = lane & 3;

    float c[4][4][4];
#pragma unroll
    for (int i = 0; i < 4; i++)
#pragma unroll
        for (int j = 0; j < 4; j++)
#pragma unroll
            for (int k = 0; k < 4; k++) c[i][j][k] = 0.f;

    const int aRow0 = tid >> 2,        aK0 = (tid & 3) * 4;
    const int aRow1 = (tid >> 2) + 64;
    const int bK0 = tid >> 5,          bN = (tid & 31) * 4;
    const int bK1 = (tid >> 5) + 8;

    const float* Ap0; const float* Ap1;
    {
        const int r = by * 128 + aRow0;
        const int bi2 = (r >= n_m) ? 1 : 0;
        Ap0 = g_o + ((size_t)bi2 * NTc + (r - bi2 * n_m) + modoff) * DIc + aK0;
    }
    {
        const int r = by * 128 + aRow1;
        const int bi2 = (r >= n_m) ? 1 : 0;
        Ap1 = g_o + ((size_t)bi2 * NTc + (r - bi2 * n_m) + modoff) * DIc + aK0;
    }
    const float* Bp0 = Wout + (size_t)bK0 * Nn + bx * 128 + bN;
    const float* Bp1 = Wout + (size_t)bK1 * Nn + bx * 128 + bN;

    const int niter = DIc >> 4;   // 64
    float4 ar0 = *(const float4*)Ap0;
    float4 ar1 = *(const float4*)Ap1;
    float4 br0 = *(const float4*)Bp0;
    float4 br1 = *(const float4*)Bp1;

    *(uint4*)(&As[0][aRow0 * APAD + aK0]) = cvt4(ar0);
    *(uint4*)(&As[0][aRow1 * APAD + aK0]) = cvt4(ar1);
    *(uint4*)(&Bs[0][bK0 * BPAD + bN])    = cvt4(br0);
    *(uint4*)(&Bs[0][bK1 * BPAD + bN])    = cvt4(br1);
    __syncthreads();

    for (int it = 0; it < niter; ++it) {
        const int cur = it & 1;
        const bool more = (it + 1 < niter);
        if (more) {
            const int o = (it + 1) * 16;
            ar0 = *(const float4*)(Ap0 + o);
            ar1 = *(const float4*)(Ap1 + o);
            br0 = *(const float4*)(Bp0 + (size_t)o * Nn);
            br1 = *(const float4*)(Bp1 + (size_t)o * Nn);
        }
        const uint32_t* Ac = As[cur];
        const uint32_t* Bc = Bs[cur];
#pragma unroll
        for (int kc = 0; kc < 2; kc++) {
            uint32_t a[4][4], b[4][2];
#pragma unroll
            for (int i = 0; i < 4; i++) {
                const int r = wm * 64 + i * 16 + gr;
                a[i][0] = Ac[r * APAD + kc * 8 + ct];
                a[i][1] = Ac[(r + 8) * APAD + kc * 8 + ct];
                a[i][2] = Ac[r * APAD + kc * 8 + ct + 4];
                a[i][3] = Ac[(r + 8) * APAD + kc * 8 + ct + 4];
            }
#pragma unroll
            for (int j = 0; j < 4; j++) {
                const int n = wn * 32 + j * 8 + gr;
                b[j][0] = Bc[(kc * 8 + ct) * BPAD + n];
                b[j][1] = Bc[(kc * 8 + ct + 4) * BPAD + n];
            }
#pragma unroll
            for (int i = 0; i < 4; i++)
#pragma unroll
                for (int j = 0; j < 4; j++) mma8(c[i][j], a[i], b[j]);
        }
        if (more) {
            const int nxt = cur ^ 1;
            *(uint4*)(&As[nxt][aRow0 * APAD + aK0]) = cvt4(ar0);
            *(uint4*)(&As[nxt][aRow1 * APAD + aK0]) = cvt4(ar1);
            *(uint4*)(&Bs[nxt][bK0 * BPAD + bN])    = cvt4(br0);
            *(uint4*)(&Bs[nxt][bK1 * BPAD + bN])    = cvt4(br1);
            __syncthreads();
        }
    }

#pragma unroll
    for (int j = 0; j < 4; j++) {
        const int col = bx * 128 + wn * 32 + j * 8 + 2 * ct;
#pragma unroll
        for (int i = 0; i < 4; i++) {
            const int r = by * 128 + wm * 64 + i * 16 + gr;
            *(float2*)(outb + (size_t)r * Nn + col) =
                make_float2(c[i][j][0], c[i][j][1]);
            *(float2*)(outb + (size_t)(r + 8) * Nn + col) =
                make_float2(c[i][j][2], c[i][j][3]);
        }
    }
}

// ---------------------------------------------------------------------------
// Launch
// ---------------------------------------------------------------------------
extern "C" void kernel_launch(void* const* d_in, const int* in_sizes, int n_in,
                              void* d_out, int out_size)
{
    const float* x0    = (const float*)d_in[0];
    const float* x1    = (const float*)d_in[1];
    const float* Wqkv0 = (const float*)d_in[2];
    const float* Wqkv1 = (const float*)d_in[3];
    const float* qg0   = (const float*)d_in[4];
    const float* kg0   = (const float*)d_in[5];
    const float* qg1   = (const float*)d_in[6];
    const float* kg1   = (const float*)d_in[7];
    const float* Wout0 = (const float*)d_in[8];
    const float* Wout1 = (const float*)d_in[9];
    float* out = (float*)d_out;

    // 1) Fused QKV GEMMs (both modalities in one launch)
    qkv_gemm_t<<<dim3(24, 32), 256>>>(x0, x1, Wqkv0, Wqkv1);

    // 2) QK RMSNorm
    qk_rmsnorm<<<(BB * Hc * NTc) / 8, 256>>>(qg0, kg0, qg1, kg1);

    // 3) Attention
    attn_t<<<dim3(NTc / 128, Hc, BB), 128>>>();

    // 4) Fused output projections
    out_gemm_t<<<224, 256>>>(Wout0, Wout1, out);
}

// round 5
// speedup vs baseline: 8.8691x; 2.0701x over previous
#include <cuda_runtime.h>
#include <cuda_fp16.h>
#include <math.h>
#include <stdint.h>

#define BB   2
#define N0c  1536
#define N1c  512
#define NTc  2048
#define Hc   16
#define Dc   64
#define DIc  1024
#define D0c  1024
#define D1c  512

// f32 scratch (pre-RMSNorm q,k)
__device__ __align__(16) float g_q[BB * Hc * NTc * Dc];
__device__ __align__(16) float g_k[BB * Hc * NTc * Dc];
// f16 scratch
__device__ __align__(16) __half g_qh[BB * Hc * NTc * Dc];
__device__ __align__(16) __half g_kh[BB * Hc * NTc * Dc];
__device__ __align__(16) __half g_vh[BB * Hc * NTc * Dc];
__device__ __align__(16) __half g_oh[BB * NTc * DIc];
// f16 input copies
__device__ __align__(16) __half h_x0[2 * 1536 * 1024];
__device__ __align__(16) __half h_x1[2 * 512 * 512];
__device__ __align__(16) __half h_w0[1024 * 3072];
__device__ __align__(16) __half h_w1[512 * 3072];
__device__ __align__(16) __half h_wo0[1024 * 1024];
__device__ __align__(16) __half h_wo1[1024 * 512];

// ---------------- PTX helpers ----------------
__device__ __forceinline__ uint32_t smem_u32(const void* p) {
    return (uint32_t)__cvta_generic_to_shared(p);
}
__device__ __forceinline__ void cp16(uint32_t s, const void* g) {
    asm volatile("cp.async.cg.shared.global [%0], [%1], 16;" :: "r"(s), "l"(g));
}
__device__ __forceinline__ void cp_commit() { asm volatile("cp.async.commit_group;"); }
template<int N> __device__ __forceinline__ void cp_wait() {
    asm volatile("cp.async.wait_group %0;" :: "n"(N));
}
__device__ __forceinline__ void ldsm4(uint32_t* r, uint32_t a) {
    asm volatile("ldmatrix.sync.aligned.m8n8.x4.shared.b16 {%0,%1,%2,%3}, [%4];"
        : "=r"(r[0]), "=r"(r[1]), "=r"(r[2]), "=r"(r[3]) : "r"(a));
}
__device__ __forceinline__ void ldsm4t(uint32_t* r, uint32_t a) {
    asm volatile("ldmatrix.sync.aligned.m8n8.x4.trans.shared.b16 {%0,%1,%2,%3}, [%4];"
        : "=r"(r[0]), "=r"(r[1]), "=r"(r[2]), "=r"(r[3]) : "r"(a));
}
__device__ __forceinline__ void mma16(float* c, const uint32_t* a, const uint32_t* b) {
    asm volatile("mma.sync.aligned.m16n8k16.row.col.f32.f16.f16.f32 "
        "{%0,%1,%2,%3}, {%4,%5,%6,%7}, {%8,%9}, {%0,%1,%2,%3};"
        : "+f"(c[0]), "+f"(c[1]), "+f"(c[2]), "+f"(c[3])
        : "r"(a[0]), "r"(a[1]), "r"(a[2]), "r"(a[3]), "r"(b[0]), "r"(b[1]));
}
__device__ __forceinline__ uint32_t h2pack(float lo, float hi) {
    uint32_t r;
    asm("cvt.rn.f16x2.f32 %0, %1, %2;" : "=r"(r) : "f"(hi), "f"(lo));
    return r;
}
// p = exp(50*tanh(dot/8/50)); |dot/8|<=8 post-RMSNorm; poly-tanh + ex2
__device__ __forceinline__ float sc_p(float dot) {
    const float sc = dot * 0.125f;
    const float u = sc * sc;
    const float t = sc * fmaf(u, fmaf(u, 3.0777494e-8f, -1.9235934e-4f), 1.4426950f);
    float p;
    asm("ex2.approx.f32 %0, %1;" : "=f"(p) : "f"(t));
    return p;
}

// ---------------- f32 -> f16 one-shot conversion ----------------
__global__ __launch_bounds__(1024) void cvt_kernel(
    const float* __restrict__ x0, const float* __restrict__ x1,
    const float* __restrict__ w0, const float* __restrict__ w1,
    const float* __restrict__ wo0, const float* __restrict__ wo1)
{
    const int i = blockIdx.x * blockDim.x + threadIdx.x;
    const float* src; __half* dst; int off;
    if      (i <  786432) { src = x0;  dst = h_x0;  off = i; }
    else if (i <  917504) { src = x1;  dst = h_x1;  off = i -  786432; }
    else if (i < 1703936) { src = w0;  dst = h_w0;  off = i -  917504; }
    else if (i < 2097152) { src = w1;  dst = h_w1;  off = i - 1703936; }
    else if (i < 2359296) { src = wo0; dst = h_wo0; off = i - 2097152; }
    else                  { src = wo1; dst = h_wo1; off = i - 2359296; }
    float4 v = ((const float4*)src)[off];
    uint2 o;
    o.x = h2pack(v.x, v.y);
    o.y = h2pack(v.z, v.w);
    ((uint2*)dst)[off] = o;
}

// ---------------- Fused QKV GEMM (f16, cp.async 2-stage) ----------------
#define AROWH 40
#define BROWH 136

__global__ __launch_bounds__(256, 2) void qkv_gemm_h()
{
    __shared__ __align__(16) __half Asm[2][128 * AROWH];
    __shared__ __align__(16) __half Bsm[2][32 * BROWH];

    const __half* X; const __half* W; int K, n_m, modoff, yb;
    if (blockIdx.y < 24) { X = h_x0; W = h_w0; K = 1024; n_m = N0c; modoff = 0;   yb = blockIdx.y; }
    else                 { X = h_x1; W = h_w1; K = 512;  n_m = N1c; modoff = N0c; yb = blockIdx.y - 24; }

    const int tid = threadIdx.x, bx = blockIdx.x;
    const int warp = tid >> 5, lane = tid & 31;
    const int wm = warp >> 2, wn = warp & 3;
    const int gr = lane >> 2, ct = lane & 3;

    const int aRow0 = tid >> 2,         aOff = (tid & 3) * 8;
    const int aRow1 = (tid + 256) >> 2;
    const int bRow0 = tid >> 4,         bOff = (tid & 15) * 8;
    const int bRow1 = (tid + 256) >> 4;
    const __half* Ag0 = X + (size_t)(yb * 128 + aRow0) * K + aOff;
    const __half* Ag1 = X + (size_t)(yb * 128 + aRow1) * K + aOff;
    const __half* Bg0 = W + (size_t)bRow0 * 3072 + bx * 128 + bOff;
    const __half* Bg1 = W + (size_t)bRow1 * 3072 + bx * 128 + bOff;
    const uint32_t As0 = smem_u32(&Asm[0][aRow0 * AROWH + aOff]);
    const uint32_t As1 = smem_u32(&Asm[0][aRow1 * AROWH + aOff]);
    const uint32_t Bs0 = smem_u32(&Bsm[0][bRow0 * BROWH + bOff]);
    const uint32_t Bs1 = smem_u32(&Bsm[0][bRow1 * BROWH + bOff]);
    const uint32_t aStg = 128 * AROWH * 2, bStg = 32 * BROWH * 2;

    const int arl = lane & 15, ach = (lane >> 4) * 8;

    float c[4][4][4];
#pragma unroll
    for (int i = 0; i < 4; i++)
#pragma unroll
        for (int j = 0; j < 4; j++)
#pragma unroll
            for (int k = 0; k < 4; k++) c[i][j][k] = 0.f;

    const int niter = K >> 5;
#pragma unroll
    for (int s = 0; s < 2; s++) {
        const int o = s * 32;
        cp16(As0 + s * aStg, Ag0 + o); cp16(As1 + s * aStg, Ag1 + o);
        cp16(Bs0 + s * bStg, Bg0 + (size_t)o * 3072);
        cp16(Bs1 + s * bStg, Bg1 + (size_t)o * 3072);
        cp_commit();
    }
    cp_wait<1>(); __syncthreads();

    for (int it = 0; it < niter; ++it) {
        const int cur = it & 1;
        const uint32_t aB = smem_u32(&Asm[cur][0]);
        const uint32_t bB = smem_u32(&Bsm[cur][0]);
#pragma unroll
        for (int kc = 0; kc < 2; kc++) {
            uint32_t a[4][4], b[4][2], tt[4];
#pragma unroll
            for (int i = 0; i < 4; i++)
                ldsm4(a[i], aB + 2 * ((wm * 64 + i * 16 + arl) * AROWH + kc * 16 + ach));
#pragma unroll
            for (int jj = 0; jj < 2; jj++) {
                ldsm4t(tt, bB + 2 * ((kc * 16 + arl) * BROWH + wn * 32 + jj * 16 + ach));
                b[jj * 2][0] = tt[0]; b[jj * 2][1] = tt[1];
                b[jj * 2 + 1][0] = tt[2]; b[jj * 2 + 1][1] = tt[3];
            }
#pragma unroll
            for (int i = 0; i < 4; i++)
#pragma unroll
                for (int j = 0; j < 4; j++) mma16(c[i][j], a[i], b[j]);
        }
        __syncthreads();
        if (it + 2 < niter) {
            const int o = (it + 2) * 32;
            cp16(As0 + cur * aStg, Ag0 + o); cp16(As1 + cur * aStg, Ag1 + o);
            cp16(Bs0 + cur * bStg, Bg0 + (size_t)o * 3072);
            cp16(Bs1 + cur * bStg, Bg1 + (size_t)o * 3072);
            cp_commit(); cp_wait<1>();
        } else {
            cp_wait<0>();
        }
        __syncthreads();
    }

    // Epilogue: q,k -> f32 scratch; v -> f16
#pragma unroll
    for (int j = 0; j < 4; j++) {
        const int gc = bx * 128 + wn * 32 + j * 8 + 2 * ct;
        const int qkvI = gc >> 10;
        const int hh = (gc >> 6) & (Hc - 1);
        const int dd = gc & (Dc - 1);
#pragma unroll
        for (int i = 0; i < 4; i++) {
#pragma unroll
            for (int hr = 0; hr < 2; hr++) {
                const int r = yb * 128 + wm * 64 + i * 16 + gr + hr * 8;
                const int bi2 = (r >= n_m) ? 1 : 0;
                const int tok = r - bi2 * n_m + modoff;
                const size_t base = ((size_t)(bi2 * Hc + hh) * NTc + tok) * Dc + dd;
                const float v0 = c[i][j][hr * 2], v1 = c[i][j][hr * 2 + 1];
                if (qkvI == 2) {
                    *(uint32_t*)(g_vh + base) = h2pack(v0, v1);
                } else {
                    float* dst = qkvI ? g_k : g_q;
                    *(float2*)(dst + base) = make_float2(v0, v1);
                }
            }
        }
    }
}

// ---------------- QK RMSNorm: f32 in -> f16 out ----------------
__global__ __launch_bounds__(256) void qk_rmsnorm(
    const float* __restrict__ qg0, const float* __restrict__ kg0,
    const float* __restrict__ qg1, const float* __restrict__ kg1)
{
    const int warp = (blockIdx.x * blockDim.x + threadIdx.x) >> 5;
    const int lane = threadIdx.x & 31;
    if (warp >= BB * Hc * NTc) return;

    const int h   = (warp >> 11) & (Hc - 1);
    const int tok = warp & (NTc - 1);
    const int mod = (tok >= N0c) ? 1 : 0;
    const float* qg = mod ? qg1 : qg0;
    const float* kg = mod ? kg1 : kg0;
    const float gq0 = qg[h * 64 + lane], gq1 = qg[h * 64 + lane + 32];
    const float gk0 = kg[h * 64 + lane], gk1 = kg[h * 64 + lane + 32];

    {
        const float* p = g_q + (size_t)warp * 64;
        float a = p[lane], b = p[lane + 32];
        float ss = a * a + b * b;
#pragma unroll
        for (int off = 16; off > 0; off >>= 1) ss += __shfl_xor_sync(~0u, ss, off);
        float s = 8.0f / fmaxf(sqrtf(ss), 1e-12f);
        g_qh[(size_t)warp * 64 + lane]      = __float2half_rn(a * s * gq0);
        g_qh[(size_t)warp * 64 + lane + 32] = __float2half_rn(b * s * gq1);
    }
    {
        const float* p = g_k + (size_t)warp * 64;
        float a = p[lane], b = p[lane + 32];
        float ss = a * a + b * b;
#pragma unroll
        for (int off = 16; off > 0; off >>= 1) ss += __shfl_xor_sync(~0u, ss, off);
        float s = 8.0f / fmaxf(sqrtf(ss), 1e-12f);
        g_kh[(size_t)warp * 64 + lane]      = __float2half_rn(a * s * gk0);
        g_kh[(size_t)warp * 64 + lane + 32] = __float2half_rn(b * s * gk1);
    }
}

// ---------------- Attention (f16 mma, cp.async 2-stage) ----------------
#define KVROWH 72

__global__ __launch_bounds__(128, 2) void attn_h()
{
    __shared__ __align__(16) __half S0[2 * 64 * KVROWH];   // K | V
    __shared__ __align__(16) __half S1[2 * 64 * KVROWH];   // (also Q staging 128x72)

    const int tid  = threadIdx.x;
    const int warp = tid >> 5, lane = tid & 31;
    const int gr = lane >> 2, ct = lane & 3;
    const int h  = blockIdx.y, bi = blockIdx.z;

    const size_t hb = (size_t)(bi * Hc + h) * NTc * Dc;
    const __half* qh = g_qh + hb + (size_t)blockIdx.x * 128 * Dc;
    const __half* kh = g_kh + hb;
    const __half* vh = g_vh + hb;

    const int cRow = tid >> 3, cOff = (tid & 7) * 8;

    // Q -> S1 (group 0)
#pragma unroll
    for (int p = 0; p < 8; p++) {
        const int row = cRow + p * 16;
        cp16(smem_u32(&S1[row * KVROWH + cOff]), qh + row * Dc + cOff);
    }
    cp_commit();
    // K/V tile 0 -> S0 (group 1)
#pragma unroll
    for (int p = 0; p < 4; p++) {
        const int row = cRow + p * 16;
        cp16(smem_u32(&S0[row * KVROWH + cOff]), kh + (size_t)row * Dc + cOff);
        cp16(smem_u32(&S0[(64 + row) * KVROWH + cOff]), vh + (size_t)row * Dc + cOff);
    }
    cp_commit();
    cp_wait<1>(); __syncthreads();

    const int arl = lane & 15, ach = (lane >> 4) * 8;
    uint32_t qa[4][2][4];
    {
        const uint32_t qb = smem_u32(S1);
#pragma unroll
        for (int ck = 0; ck < 4; ck++)
#pragma unroll
            for (int m = 0; m < 2; m++)
                ldsm4(qa[ck][m], qb + 2 * ((warp * 32 + m * 16 + arl) * KVROWH + ck * 16 + ach));
    }
    __syncthreads();
    // K/V tile 1 -> S1 (group 2)
#pragma unroll
    for (int p = 0; p < 4; p++) {
        const int row = cRow + p * 16;
        cp16(smem_u32(&S1[row * KVROWH + cOff]), kh + (size_t)(64 + row) * Dc + cOff);
        cp16(smem_u32(&S1[(64 + row) * KVROWH + cOff]), vh + (size_t)(64 + row) * Dc + cOff);
    }
    cp_commit();
    cp_wait<1>(); __syncthreads();

    float oc[2][8][4];
#pragma unroll
    for (int m = 0; m < 2; m++)
#pragma unroll
        for (int n = 0; n < 8; n++)
#pragma unroll
            for (int k = 0; k < 4; k++) oc[m][n][k] = 0.f;
    float l[2][2] = {{0.f, 0.f}, {0.f, 0.f}};

    const int krl = lane & 7;
    const int kof = ((lane >> 3) & 1) * 8 + ((lane >> 4) & 1) * 16;

    const int NT_TILES = NTc / 64;
    for (int t = 0; t < NT_TILES; t++) {
        const uint32_t sb = smem_u32((t & 1) ? S1 : S0);
        const uint32_t vbB = sb + 2 * (64 * KVROWH);

#pragma unroll
        for (int jj = 0; jj < 4; jj++) {
            uint32_t kb[2][4][2];
#pragma unroll
            for (int j01 = 0; j01 < 2; j01++) {
                const int j = jj * 2 + j01;
                uint32_t tt[4];
#pragma unroll
                for (int idx = 0; idx < 2; idx++) {
                    ldsm4(tt, sb + 2 * ((j * 8 + krl) * KVROWH + idx * 32 + kof));
                    kb[j01][idx * 2][0] = tt[0]; kb[j01][idx * 2][1] = tt[1];
                    kb[j01][idx * 2 + 1][0] = tt[2]; kb[j01][idx * 2 + 1][1] = tt[3];
                }
            }
            float s[2][2][4];
#pragma unroll
            for (int j01 = 0; j01 < 2; j01++)
#pragma unroll
                for (int m = 0; m < 2; m++)
#pragma unroll
                    for (int k = 0; k < 4; k++) s[j01][m][k] = 0.f;
#pragma unroll
            for (int ck = 0; ck < 4; ck++)
#pragma unroll
                for (int j01 = 0; j01 < 2; j01++) {
                    mma16(s[j01][0], qa[ck][0], kb[j01][ck]);
                    mma16(s[j01][1], qa[ck][1], kb[j01][ck]);
                }
            uint32_t pa[2][4];
#pragma unroll
            for (int m = 0; m < 2; m++) {
                const float p00 = sc_p(s[0][m][0]), p01 = sc_p(s[0][m][1]);
                const float p02 = sc_p(s[0][m][2]), p03 = sc_p(s[0][m][3]);
                const float p10 = sc_p(s[1][m][0]), p11 = sc_p(s[1][m][1]);
                const float p12 = sc_p(s[1][m][2]), p13 = sc_p(s[1][m][3]);
                l[m][0] += p00 + p01 + p10 + p11;
                l[m][1] += p02 + p03 + p12 + p13;
                pa[m][0] = h2pack(p00, p01);
                pa[m][1] = h2pack(p02, p03);
                pa[m][2] = h2pack(p10, p11);
                pa[m][3] = h2pack(p12, p13);
            }
            uint32_t vb[8][2], tt[4];
#pragma unroll
            for (int nb2 = 0; nb2 < 4; nb2++) {
                ldsm4t(tt, vbB + 2 * ((jj * 16 + arl) * KVROWH + nb2 * 16 + ach));
                vb[nb2 * 2][0] = tt[0]; vb[nb2 * 2][1] = tt[1];
                vb[nb2 * 2 + 1][0] = tt[2]; vb[nb2 * 2 + 1][1] = tt[3];
            }
#pragma unroll
            for (int nb = 0; nb < 8; nb++) {
                mma16(oc[0][nb], pa[0], vb[nb]);
                mma16(oc[1][nb], pa[1], vb[nb]);
            }
        }
        __syncthreads();
        if (t + 2 < NT_TILES) {
            __half* dst = (t & 1) ? S1 : S0;
            const size_t kbase = (size_t)(t + 2) * 64;
#pragma unroll
            for (int p = 0; p < 4; p++) {
                const int row = cRow + p * 16;
                cp16(smem_u32(&dst[row * KVROWH + cOff]), kh + (kbase + row) * Dc + cOff);
                cp16(smem_u32(&dst[(64 + row) * KVROWH + cOff]), vh + (kbase + row) * Dc + cOff);
            }
            cp_commit(); cp_wait<1>();
        } else {
            cp_wait<0>();
        }
        __syncthreads();
    }

#pragma unroll
    for (int m = 0; m < 2; m++)
#pragma unroll
        for (int rr = 0; rr < 2; rr++) {
            l[m][rr] += __shfl_xor_sync(~0u, l[m][rr], 1);
            l[m][rr] += __shfl_xor_sync(~0u, l[m][rr], 2);
        }
#pragma unroll
    for (int m = 0; m < 2; m++) {
        const int row = blockIdx.x * 128 + warp * 32 + m * 16 + gr;
        __half* op0 = g_oh + ((size_t)bi * NTc + row) * DIc + h * Dc;
        __half* op1 = op0 + 8 * DIc;
        const float i0 = 1.0f / l[m][0];
        const float i1 = 1.0f / l[m][1];
#pragma unroll
        for (int nb = 0; nb < 8; nb++) {
            const int col = nb * 8 + 2 * ct;
            *(uint32_t*)(op0 + col) = h2pack(oc[m][nb][0] * i0, oc[m][nb][1] * i0);
            *(uint32_t*)(op1 + col) = h2pack(oc[m][nb][2] * i1, oc[m][nb][3] * i1);
        }
    }
}

// ---------------- Fused out proj (f16, cp.async 2-stage) ----------------
__global__ __launch_bounds__(256, 2) void out_gemm_h(float* __restrict__ outp)
{
    __shared__ __align__(16) __half Asm[2][128 * AROWH];
    __shared__ __align__(16) __half Bsm[2][32 * BROWH];

    const __half* W; float* outb; int Nn, n_m, modoff, bx, by;
    if (blockIdx.x < 192) {
        W = h_wo0; outb = outp; Nn = D0c; n_m = N0c; modoff = 0;
        bx = blockIdx.x & 7; by = blockIdx.x >> 3;
    } else {
        const int b2 = blockIdx.x - 192;
        W = h_wo1; outb = outp + (size_t)BB * N0c * D0c; Nn = D1c; n_m = N1c; modoff = N0c;
        bx = b2 & 3; by = b2 >> 2;
    }

    const int tid = threadIdx.x;
    const int warp = tid >> 5, lane = tid & 31;
    const int wm = warp >> 2, wn = warp & 3;
    const int gr = lane >> 2, ct = lane & 3;

    const int aRow0 = tid >> 2,         aOff = (tid & 3) * 8;
    const int aRow1 = (tid + 256) >> 2;
    const int bRow0 = tid >> 4,         bOff = (tid & 15) * 8;
    const int bRow1 = (tid + 256) >> 4;

    const __half* Ag0; const __half* Ag1;
    {
        const int r = by * 128 + aRow0;
        const int bi2 = (r >= n_m) ? 1 : 0;
        Ag0 = g_oh + ((size_t)bi2 * NTc + (r - bi2 * n_m) + modoff) * DIc + aOff;
    }
    {
        const int r = by * 128 + aRow1;
        const int bi2 = (r >= n_m) ? 1 : 0;
        Ag1 = g_oh + ((size_t)bi2 * NTc + (r - bi2 * n_m) + modoff) * DIc + aOff;
    }
    const __half* Bg0 = W + (size_t)bRow0 * Nn + bx * 128 + bOff;
    const __half* Bg1 = W + (size_t)bRow1 * Nn + bx * 128 + bOff;
    const uint32_t As0 = smem_u32(&Asm[0][aRow0 * AROWH + aOff]);
    const uint32_t As1 = smem_u32(&Asm[0][aRow1 * AROWH + aOff]);
    const uint32_t Bs0 = smem_u32(&Bsm[0][bRow0 * BROWH + bOff]);
    const uint32_t Bs1 = smem_u32(&Bsm[0][bRow1 * BROWH + bOff]);
    const uint32_t aStg = 128 * AROWH * 2, bStg = 32 * BROWH * 2;

    const int arl = lane & 15, ach = (lane >> 4) * 8;

    float c[4][4][4];
#pragma unroll
    for (int i = 0; i < 4; i++)
#pragma unroll
        for (int j = 0; j < 4; j++)
#pragma unroll
            for (int k = 0; k < 4; k++) c[i][j][k] = 0.f;

    const int niter = DIc >> 5;   // 32
#pragma unroll
    for (int s = 0; s < 2; s++) {
        const int o = s * 32;
        cp16(As0 + s * aStg, Ag0 + o); cp16(As1 + s * aStg, Ag1 + o);
        cp16(Bs0 + s * bStg, Bg0 + (size_t)o * Nn);
        cp16(Bs1 + s * bStg, Bg1 + (size_t)o * Nn);
        cp_commit();
    }
    cp_wait<1>(); __syncthreads();

    for (int it = 0; it < niter; ++it) {
        const int cur = it & 1;
        const uint32_t aB = smem_u32(&Asm[cur][0]);
        const uint32_t bB = smem_u32(&Bsm[cur][0]);
#pragma unroll
        for (int kc = 0; kc < 2; kc++) {
            uint32_t a[4][4], b[4][2], tt[4];
#pragma unroll
            for (int i = 0; i < 4; i++)
                ldsm4(a[i], aB + 2 * ((wm * 64 + i * 16 + arl) * AROWH + kc * 16 + ach));
#pragma unroll
            for (int jj = 0; jj < 2; jj++) {
                ldsm4t(tt, bB + 2 * ((kc * 16 + arl) * BROWH + wn * 32 + jj * 16 + ach));
                b[jj * 2][0] = tt[0]; b[jj * 2][1] = tt[1];
                b[jj * 2 + 1][0] = tt[2]; b[jj * 2 + 1][1] = tt[3];
            }
#pragma unroll
            for (int i = 0; i < 4; i++)
#pragma unroll
                for (int j = 0; j < 4; j++) mma16(c[i][j], a[i], b[j]);
        }
        __syncthreads();
        if (it + 2 < niter) {
            const int o = (it + 2) * 32;
            cp16(As0 + cur * aStg, Ag0 + o); cp16(As1 + cur * aStg, Ag1 + o);
            cp16(Bs0 + cur * bStg, Bg0 + (size_t)o * Nn);
            cp16(Bs1 + cur * bStg, Bg1 + (size_t)o * Nn);
            cp_commit(); cp_wait<1>();
        } else {
            cp_wait<0>();
        }
        __syncthreads();
    }

#pragma unroll
    for (int j = 0; j < 4; j++) {
        const int col = bx * 128 + wn * 32 + j * 8 + 2 * ct;
#pragma unroll
        for (int i = 0; i < 4; i++) {
            const int r = by * 128 + wm * 64 + i * 16 + gr;
            *(float2*)(outb + (size_t)r * Nn + col) = make_float2(c[i][j][0], c[i][j][1]);
            *(float2*)(outb + (size_t)(r + 8) * Nn + col) = make_float2(c[i][j][2], c[i][j][3]);
        }
    }
}

// ---------------- Launch ----------------
extern "C" void kernel_launch(void* const* d_in, const int* in_sizes, int n_in,
                              void* d_out, int out_size)
{
    const float* x0    = (const float*)d_in[0];
    const float* x1    = (const float*)d_in[1];
    const float* Wqkv0 = (const float*)d_in[2];
    const float* Wqkv1 = (const float*)d_in[3];
    const float* qg0   = (const float*)d_in[4];
    const float* kg0   = (const float*)d_in[5];
    const float* qg1   = (const float*)d_in[6];
    const float* kg1   = (const float*)d_in[7];
    const float* Wout0 = (const float*)d_in[8];
    const float* Wout1 = (const float*)d_in[9];
    float* out = (float*)d_out;

    cvt_kernel<<<2432, 1024>>>(x0, x1, Wqkv0, Wqkv1, Wout0, Wout1);
    qkv_gemm_h<<<dim3(24, 32), 256>>>();
    qk_rmsnorm<<<(BB * Hc * NTc) / 8, 256>>>(qg0, kg0, qg1, kg1);
    attn_h<<<dim3(NTc / 128, Hc, BB), 128>>>();
    out_gemm_h<<<224, 256>>>(out);
}